// round 9
// baseline (speedup 1.0000x reference)
#include <cuda_runtime.h>
#include <math.h>
#include <stdint.h>

constexpr int NB    = 32;
constexpr int NKV   = 2048;
constexpr int NHID  = 2560;
constexpr int NHEADS= 32;
constexpr int NHD   = 80;
constexpr int NNI   = 10240;
constexpr int NQKV  = 3 * NHID;

// Attention tiling: block = (8-head group, batch, 64-token chunk)
constexpr int HG     = 8;            // heads per block
constexpr int NG     = NHEADS / HG;  // 4 head groups
constexpr int CH     = 64;           // tokens per chunk
constexpr int NCHUNK = NKV / CH;     // 32

// GEMM tiling: block = 256 thr (8 warps), tile 32m x 128n x 64k
constexpr int GK  = 64;
constexpr int GN  = 128;
constexpr int XS_STRIDE = 68;
constexpr int WS_STRIDE = 64;
constexpr int XS_FLOATS = 32 * XS_STRIDE;
constexpr int WS_FLOATS = GN * WS_STRIDE;
constexpr int SMEM_FLOATS = 2 * (XS_FLOATS + WS_FLOATS);
constexpr int SMEM_BYTES  = SMEM_FLOATS * 4;       // 82944

// Scratch (allocation-free: device globals); per-GEMM partials (stream-safe).
__device__ __align__(16) float g_x[NB * NHID];
__device__ __align__(16) float g_qkv[NB * NQKV];
__device__ __align__(16) float g_attn[NB * NHID];
__device__ __align__(16) float g_attn_out[NB * NHID];
__device__ __align__(16) float g_hmlp[NB * NNI];
__device__ __align__(16) float g_part_qkv[4  * 32 * NQKV];
__device__ __align__(16) float g_part_out[10 * 32 * NHID];
__device__ __align__(16) float g_part_fc1[4  * 32 * NNI];
__device__ __align__(16) float g_part_fc2[16 * 32 * NHID];
__device__ __align__(16) float g_pm[NB * NHEADS * NCHUNK];
__device__ __align__(16) float g_pl[NB * NHEADS * NCHUNK];
__device__ __align__(16) float g_po[NB * NHEADS * NCHUNK * NHD];

// ---------------------------------------------------------------------------
__device__ __forceinline__ uint32_t f2tf32(float x) {
    uint32_t r;
    asm("cvt.rna.tf32.f32 %0, %1;" : "=r"(r) : "f"(x));
    return r;
}

__device__ __forceinline__ void mma_tf32(float* d, const uint32_t* a,
                                         uint32_t b0, uint32_t b1) {
    asm volatile(
        "mma.sync.aligned.m16n8k8.row.col.f32.tf32.tf32.f32 "
        "{%0,%1,%2,%3}, {%4,%5,%6,%7}, {%8,%9}, {%0,%1,%2,%3};\n"
        : "+f"(d[0]), "+f"(d[1]), "+f"(d[2]), "+f"(d[3])
        : "r"(a[0]), "r"(a[1]), "r"(a[2]), "r"(a[3]), "r"(b0), "r"(b1));
}

__device__ __forceinline__ void cp_async16(void* dst, const void* src) {
    uint32_t s = (uint32_t)__cvta_generic_to_shared(dst);
    asm volatile("cp.async.cg.shared.global [%0], [%1], 16;\n"
                 :: "r"(s), "l"(src));
}

__device__ __forceinline__ float dot4(float4 a, float4 b) {
    return a.x * b.x + a.y * b.y + a.z * b.z + a.w * b.w;
}

// ---------------------------------------------------------------------------
__global__ __launch_bounds__(256) void ln_kernel(
    const float* __restrict__ hs, const float* __restrict__ gam,
    const float* __restrict__ bet, float* __restrict__ xout)
{
    int b = blockIdx.x;
    const float* row = hs + b * NHID;
    float s = 0.f, s2 = 0.f;
    for (int i = threadIdx.x; i < NHID / 4; i += blockDim.x) {
        float4 v = reinterpret_cast<const float4*>(row)[i];
        s  += v.x + v.y + v.z + v.w;
        s2 += v.x * v.x + v.y * v.y + v.z * v.z + v.w * v.w;
    }
    __shared__ float rs[256], rs2[256];
    rs[threadIdx.x] = s; rs2[threadIdx.x] = s2;
    __syncthreads();
    for (int o = 128; o > 0; o >>= 1) {
        if (threadIdx.x < o) {
            rs[threadIdx.x]  += rs[threadIdx.x + o];
            rs2[threadIdx.x] += rs2[threadIdx.x + o];
        }
        __syncthreads();
    }
    float mu  = rs[0] / NHID;
    float var = rs2[0] / NHID - mu * mu;
    float inv = rsqrtf(var + 1e-5f);
    for (int i = threadIdx.x; i < NHID; i += blockDim.x) {
        xout[b * NHID + i] = (row[i] - mu) * inv * gam[i] + bet[i];
    }
}

// ---------------------------------------------------------------------------
// tf32 split-K GEMM, cp.async double-buffered. 256 thr = 8 warps.
// ---------------------------------------------------------------------------
__global__ __launch_bounds__(256) void gemm_tf32_kernel(
    const float* __restrict__ X, const float* __restrict__ W,
    float* __restrict__ part, int N, int K, int Kper)
{
    extern __shared__ float sm[];
    float* XsBuf[2] = { sm, sm + XS_FLOATS };
    float* WsBuf[2] = { sm + 2 * XS_FLOATS, sm + 2 * XS_FLOATS + WS_FLOATS };

    int tid  = threadIdx.x;
    int w    = tid >> 5;
    int lane = tid & 31;
    int g    = lane >> 2;
    int t    = lane & 3;

    int nbase  = blockIdx.x * GN;
    int ks     = blockIdx.y * Kper;
    int ntiles = Kper / GK;

    float d[2][2][4];
#pragma unroll
    for (int m = 0; m < 2; m++)
#pragma unroll
        for (int s = 0; s < 2; s++)
#pragma unroll
            for (int f = 0; f < 4; f++) d[m][s][f] = 0.f;

    auto stageW = [&](int st, int kt) {
        float* ws = WsBuf[st];
#pragma unroll
        for (int i = 0; i < 8; i++) {
            int c   = tid + i * 256;
            int row = c >> 4;
            int cc  = (c & 15) * 4;
            int pc  = cc ^ ((row & 7) << 2);
            cp_async16(ws + row * WS_STRIDE + pc,
                       W + (size_t)(nbase + row) * K + kt + cc);
        }
        asm volatile("cp.async.commit_group;\n");
    };
    float4 xr[2];
    auto loadX = [&](int kt) {
#pragma unroll
        for (int i = 0; i < 2; i++) {
            int c   = tid + i * 256;
            int row = c >> 4;
            int cc  = (c & 15) * 4;
            xr[i] = *reinterpret_cast<const float4*>(X + (size_t)row * K + kt + cc);
        }
    };
    auto storeX = [&](int st) {
        float* xs = XsBuf[st];
#pragma unroll
        for (int i = 0; i < 2; i++) {
            int c   = tid + i * 256;
            int row = c >> 4;
            int cc  = (c & 15) * 4;
            uint4 u;
            u.x = f2tf32(xr[i].x); u.y = f2tf32(xr[i].y);
            u.z = f2tf32(xr[i].z); u.w = f2tf32(xr[i].w);
            *reinterpret_cast<uint4*>(xs + row * XS_STRIDE + cc) = u;
        }
    };

    stageW(0, ks);
    loadX(ks);
    storeX(0);
    asm volatile("cp.async.wait_group 0;\n");
    __syncthreads();

    for (int it = 0; it < ntiles; it++) {
        int cur = it & 1;
        bool more = (it + 1 < ntiles);
        if (more) {
            stageW(cur ^ 1, ks + (it + 1) * GK);
            loadX(ks + (it + 1) * GK);
        }

        const uint32_t* xs = reinterpret_cast<const uint32_t*>(XsBuf[cur]);
        const float*    ws = WsBuf[cur];
        int sw = (g << 2);
#pragma unroll
        for (int k8 = 0; k8 < GK; k8 += 8) {
            uint32_t a0[4], a1[4];
            a0[0] = xs[(g     ) * XS_STRIDE + k8 + t];
            a0[1] = xs[(g +  8) * XS_STRIDE + k8 + t];
            a0[2] = xs[(g     ) * XS_STRIDE + k8 + t + 4];
            a0[3] = xs[(g +  8) * XS_STRIDE + k8 + t + 4];
            a1[0] = xs[(g + 16) * XS_STRIDE + k8 + t];
            a1[1] = xs[(g + 24) * XS_STRIDE + k8 + t];
            a1[2] = xs[(g + 16) * XS_STRIDE + k8 + t + 4];
            a1[3] = xs[(g + 24) * XS_STRIDE + k8 + t + 4];
#pragma unroll
            for (int s = 0; s < 2; s++) {
                int row = w * 16 + s * 8 + g;
                uint32_t b0 = f2tf32(ws[row * WS_STRIDE + ((k8 + t    ) ^ sw)]);
                uint32_t b1 = f2tf32(ws[row * WS_STRIDE + ((k8 + t + 4) ^ sw)]);
                mma_tf32(d[0][s], a0, b0, b1);
                mma_tf32(d[1][s], a1, b0, b1);
            }
        }

        if (more) {
            storeX(cur ^ 1);
            asm volatile("cp.async.wait_group 0;\n");
        }
        __syncthreads();
    }

    float* pbase = part + (size_t)blockIdx.y * 32 * N;
#pragma unroll
    for (int m = 0; m < 2; m++) {
#pragma unroll
        for (int s = 0; s < 2; s++) {
            int col = nbase + w * 16 + s * 8 + 2 * t;
            int r0  = g + m * 16;
            float2 lo = make_float2(d[m][s][0], d[m][s][1]);
            float2 hi = make_float2(d[m][s][2], d[m][s][3]);
            *reinterpret_cast<float2*>(pbase + (size_t)r0 * N + col)       = lo;
            *reinterpret_cast<float2*>(pbase + (size_t)(r0 + 8) * N + col) = hi;
        }
    }
}

// ---------------------------------------------------------------------------
template <int EPI>
__global__ __launch_bounds__(256) void reduce_kernel(
    const float* __restrict__ part, const float* __restrict__ bias,
    float* __restrict__ C, int N, int KS,
    const float* __restrict__ add1, const float* __restrict__ add2)
{
    int id = blockIdx.x * 256 + threadIdx.x;
    if (id >= 32 * N) return;
    int j = id % N;
    float s = 0.f;
    for (int z = 0; z < KS; z++) s += part[(size_t)z * 32 * N + id];
    float val = s + bias[j];
    if (EPI == 1) {
        float u = val;
        float th = tanhf(0.7978845608028654f * (u + 0.044715f * u * u * u));
        val = 0.5f * u * (1.f + th);
    } else if (EPI == 2) {
        val += add1[id] + add2[id];
    }
    C[id] = val;
}

// ---------------------------------------------------------------------------
__global__ __launch_bounds__(512) void rope_kernel(
    const int* __restrict__ ctxl, float* __restrict__ qkv)
{
    int b = blockIdx.x;
    int t = threadIdx.x;
    int h = t >> 4;
    int i = t & 15;
    float pos = (float)ctxl[b];
    float inv_freq = expf(-(float)(2 * i) / 32.0f * 9.210340371976184f);
    float ang = pos * inv_freq;
    float sn, cs;
    sincosf(ang, &sn, &cs);

    float* q = qkv + (size_t)b * NQKV + h * NHD;
    float x1 = q[i], x2 = q[i + 16];
    q[i]      = x1 * cs - x2 * sn;
    q[i + 16] = x2 * cs + x1 * sn;

    float* k = qkv + (size_t)b * NQKV + NHID + h * NHD;
    x1 = k[i]; x2 = k[i + 16];
    k[i]      = x1 * cs - x2 * sn;
    k[i + 16] = x2 * cs + x1 * sn;
}

// ---------------------------------------------------------------------------
// Head-group coalesced flash-decode attention.
// Block = (8-head group hg, batch b, 64-token chunk z); 256 threads.
// Per token, K/V for 8 heads = 2560B contiguous = 160 float4 = 5 full-warp
// coalesced iterations (100% lanes, aligned 128B lines, zero overfetch).
// ---------------------------------------------------------------------------
__global__ __launch_bounds__(256) void attn_hg_kernel(
    const int* __restrict__ ctxl,
    const float* __restrict__ kc, const float* __restrict__ vc,
    const float* __restrict__ qkv,
    float* __restrict__ pm, float* __restrict__ pl, float* __restrict__ po)
{
    __shared__ float  sPart[CH * 161];   // per-lane dot partials (41216B)
    __shared__ float4 sQ[HG * 20];       // q for 8 heads (2560B)
    __shared__ float  sS[CH * HG];       // scores (2048B)
    __shared__ float  sP2[CH * HG];      // exp probs (2048B)

    int hg = blockIdx.x, b = blockIdx.y, z = blockIdx.z;
    int tid = threadIdx.x;
    int w = tid >> 5, lane = tid & 31;
    int ctx = ctxl[b];
    int L = ctx + 1;
    int s0 = z * CH;
    int s1 = min(L, s0 + CH);
    int cnt = s1 - s0;

    if (s0 >= L) {
        // empty chunk: mark with -inf/0; combine weights it to exactly 0.
        if (tid < HG) {
            int idx = (b * NHEADS + hg * HG + tid) * NCHUNK + z;
            pm[idx] = -1e30f;
            pl[idx] = 0.f;
        }
        return;
    }

    const float4* qkv4 = reinterpret_cast<const float4*>(qkv);
    const float4* qb   = qkv4 + (size_t)b * (NQKV / 4) + hg * 160;
    const float4* knew = qkv4 + (size_t)b * (NQKV / 4) + (NHID / 4) + hg * 160;
    const float4* vnew = qkv4 + (size_t)b * (NQKV / 4) + 2 * (NHID / 4) + hg * 160;
    const float4* kc4  = reinterpret_cast<const float4*>(kc);
    const float4* vc4  = reinterpret_cast<const float4*>(vc);

    if (tid < 160) sQ[tid] = qb[tid];
    __syncthreads();

    float4 q0 = sQ[lane], q1 = sQ[lane + 32], q2 = sQ[lane + 64],
           q3 = sQ[lane + 96], q4 = sQ[lane + 128];

    const float scale = 0.11180339887498948f; // 80^-0.5

    // Pass 1: K dot partials; warp w handles tokens w, w+8, ...
    for (int t = w; t < cnt; t += 8) {
        int s = s0 + t;
        const float4* kr = (s == ctx)
            ? knew
            : kc4 + ((size_t)b * NKV + s) * 640 + hg * 160;
        float4 k0 = kr[lane];
        float4 k1 = kr[lane + 32];
        float4 k2 = kr[lane + 64];
        float4 k3 = kr[lane + 96];
        float4 k4 = kr[lane + 128];
        float* sp = sPart + t * 161;
        sp[lane]       = dot4(k0, q0);
        sp[lane + 32]  = dot4(k1, q1);
        sp[lane + 64]  = dot4(k2, q2);
        sp[lane + 96]  = dot4(k3, q3);
        sp[lane + 128] = dot4(k4, q4);
    }
    __syncthreads();

    // Score sum: 512 (token, head) slots; each thread takes 2.
#pragma unroll
    for (int r = 0; r < 2; r++) {
        int slot = tid + r * 256;
        int t = slot & 63;
        int h = slot >> 6;
        float sc = -1e30f;
        if (t < cnt) {
            const float* sp = sPart + t * 161 + h * 20;
            float s = 0.f;
#pragma unroll
            for (int j = 0; j < 20; j++) s += sp[j];
            sc = s * scale;
        }
        sS[t * HG + h] = sc;
    }
    __syncthreads();

    // Per-head softmax: warp h owns head h (8 warps).
    {
        int h = w;
        float v0 = (lane      < cnt) ? sS[lane * HG + h]        : -1e30f;
        float v1 = (lane + 32 < cnt) ? sS[(lane + 32) * HG + h] : -1e30f;
        float mx = fmaxf(v0, v1);
#pragma unroll
        for (int o = 16; o > 0; o >>= 1)
            mx = fmaxf(mx, __shfl_xor_sync(0xffffffffu, mx, o));
        float e0 = (lane      < cnt) ? __expf(v0 - mx) : 0.f;
        float e1 = (lane + 32 < cnt) ? __expf(v1 - mx) : 0.f;
        float sum = e0 + e1;
#pragma unroll
        for (int o = 16; o > 0; o >>= 1)
            sum += __shfl_xor_sync(0xffffffffu, sum, o);
        sP2[lane * HG + h]        = e0;
        sP2[(lane + 32) * HG + h] = e1;
        if (lane == 0) {
            int idx = (b * NHEADS + hg * HG + h) * NCHUNK + z;
            pm[idx] = mx;
            pl[idx] = sum;
        }
    }
    __syncthreads();

    // Pass 2: V weighted accumulate. Output position (i, lane) fixed per thread.
    int hmap0 = (0 * 128 + lane * 4) / 80;
    int hmap1 = (1 * 128 + lane * 4) / 80;
    int hmap2 = (2 * 128 + lane * 4) / 80;
    int hmap3 = (3 * 128 + lane * 4) / 80;
    int hmap4 = (4 * 128 + lane * 4) / 80;
    float4 a0 = make_float4(0.f, 0.f, 0.f, 0.f), a1 = a0, a2 = a0, a3 = a0, a4 = a0;
    for (int t = w; t < cnt; t += 8) {
        int s = s0 + t;
        const float4* vr = (s == ctx)
            ? vnew
            : vc4 + ((size_t)b * NKV + s) * 640 + hg * 160;
        float4 v0 = vr[lane];
        float4 v1 = vr[lane + 32];
        float4 v2 = vr[lane + 64];
        float4 v3 = vr[lane + 96];
        float4 v4 = vr[lane + 128];
        const float* pp = sP2 + t * HG;
        float p0 = pp[hmap0], p1 = pp[hmap1], p2 = pp[hmap2],
              p3 = pp[hmap3], p4 = pp[hmap4];
        a0.x += p0 * v0.x; a0.y += p0 * v0.y; a0.z += p0 * v0.z; a0.w += p0 * v0.w;
        a1.x += p1 * v1.x; a1.y += p1 * v1.y; a1.z += p1 * v1.z; a1.w += p1 * v1.w;
        a2.x += p2 * v2.x; a2.y += p2 * v2.y; a2.z += p2 * v2.z; a2.w += p2 * v2.w;
        a3.x += p3 * v3.x; a3.y += p3 * v3.y; a3.z += p3 * v3.z; a3.w += p3 * v3.w;
        a4.x += p4 * v4.x; a4.y += p4 * v4.y; a4.z += p4 * v4.z; a4.w += p4 * v4.w;
    }
    __syncthreads();  // sPart reads (score phase) complete; safe to reuse

    float4* sAcc4 = reinterpret_cast<float4*>(sPart);  // [8][160] float4
    sAcc4[w * 160 + lane]       = a0;
    sAcc4[w * 160 + lane + 32]  = a1;
    sAcc4[w * 160 + lane + 64]  = a2;
    sAcc4[w * 160 + lane + 96]  = a3;
    sAcc4[w * 160 + lane + 128] = a4;
    __syncthreads();

    if (tid < 160) {
        float4 s = sAcc4[tid];
#pragma unroll
        for (int ww = 1; ww < 8; ww++) {
            float4 x = sAcc4[ww * 160 + tid];
            s.x += x.x; s.y += x.y; s.z += x.z; s.w += x.w;
        }
        int h = tid / 20;
        int d = (tid % 20) * 4;
        float* dst = po + ((size_t)(b * NHEADS + hg * HG + h) * NCHUNK + z) * NHD + d;
        *reinterpret_cast<float4*>(dst) = s;
    }
}

// ---------------------------------------------------------------------------
__global__ __launch_bounds__(128) void attn_combine_kernel(
    const float* __restrict__ pm, const float* __restrict__ pl,
    const float* __restrict__ po, float* __restrict__ attn)
{
    int h = blockIdx.x, b = blockIdx.y;
    int tid = threadIdx.x;
    if (tid >= NHD) return;
    int base = (b * NHEADS + h) * NCHUNK;

    float M = -1e30f;
    for (int z = 0; z < NCHUNK; z++) M = fmaxf(M, pm[base + z]);
    float den = 0.f, num = 0.f;
    for (int z = 0; z < NCHUNK; z++) {
        float wz = __expf(pm[base + z] - M);
        den += wz * pl[base + z];
        num += wz * po[(size_t)(base + z) * NHD + tid];
    }
    attn[(size_t)b * NHID + h * NHD + tid] = num / den;
}

// ---------------------------------------------------------------------------
extern "C" void kernel_launch(void* const* d_in, const int* in_sizes, int n_in,
                              void* d_out, int out_size)
{
    const float* hs    = (const float*)d_in[0];
    const int*   ctx   = (const int*)  d_in[1];
    const float* kc    = (const float*)d_in[2];
    const float* vc    = (const float*)d_in[3];
    const float* ln_g  = (const float*)d_in[4];
    const float* ln_b  = (const float*)d_in[5];
    const float* w_qkv = (const float*)d_in[6];
    const float* b_qkv = (const float*)d_in[7];
    const float* w_out = (const float*)d_in[8];
    const float* b_out = (const float*)d_in[9];
    const float* w_fc1 = (const float*)d_in[10];
    const float* b_fc1 = (const float*)d_in[11];
    const float* w_fc2 = (const float*)d_in[12];
    const float* b_fc2 = (const float*)d_in[13];
    float* out = (float*)d_out;

    float *px, *pqkv, *pattn, *pao, *ph;
    float *pp_qkv, *pp_out, *pp_fc1, *pp_fc2, *ppm, *ppl, *ppo;
    cudaGetSymbolAddress((void**)&px,     g_x);
    cudaGetSymbolAddress((void**)&pqkv,   g_qkv);
    cudaGetSymbolAddress((void**)&pattn,  g_attn);
    cudaGetSymbolAddress((void**)&pao,    g_attn_out);
    cudaGetSymbolAddress((void**)&ph,     g_hmlp);
    cudaGetSymbolAddress((void**)&pp_qkv, g_part_qkv);
    cudaGetSymbolAddress((void**)&pp_out, g_part_out);
    cudaGetSymbolAddress((void**)&pp_fc1, g_part_fc1);
    cudaGetSymbolAddress((void**)&pp_fc2, g_part_fc2);
    cudaGetSymbolAddress((void**)&ppm,    g_pm);
    cudaGetSymbolAddress((void**)&ppl,    g_pl);
    cudaGetSymbolAddress((void**)&ppo,    g_po);

    cudaFuncSetAttribute(gemm_tf32_kernel,
                         cudaFuncAttributeMaxDynamicSharedMemorySize, SMEM_BYTES);

    static cudaStream_t side = nullptr;
    static cudaEvent_t  ev_fork = nullptr, ev_join = nullptr;
    if (side == nullptr) {
        cudaStreamCreateWithFlags(&side, cudaStreamNonBlocking);
        cudaEventCreateWithFlags(&ev_fork, cudaEventDisableTiming);
        cudaEventCreateWithFlags(&ev_join, cudaEventDisableTiming);
    }
    cudaStream_t main0 = (cudaStream_t)0;

    // 1. LayerNorm
    ln_kernel<<<NB, 256, 0, main0>>>(hs, ln_g, ln_b, px);

    cudaEventRecord(ev_fork, main0);
    cudaStreamWaitEvent(side, ev_fork, 0);

    // ---- Track B (side): fc1 -> gelu -> fc2 ----
    {
        dim3 gr(NNI / GN, 4);
        gemm_tf32_kernel<<<gr, 256, SMEM_BYTES, side>>>(px, w_fc1, pp_fc1,
                                                        NNI, NHID, 640);
        reduce_kernel<1><<<(32 * NNI + 255) / 256, 256, 0, side>>>(
            pp_fc1, b_fc1, ph, NNI, 4, nullptr, nullptr);
        dim3 gr2(NHID / GN, 16);
        gemm_tf32_kernel<<<gr2, 256, SMEM_BYTES, side>>>(ph, w_fc2, pp_fc2,
                                                         NHID, NNI, 640);
        cudaEventRecord(ev_join, side);
    }

    // ---- Track A (main): qkv -> rope -> attention -> out-proj ----
    {
        dim3 gr(NQKV / GN, 4);   // 240 blocks: single wave at 2 blocks/SM
        gemm_tf32_kernel<<<gr, 256, SMEM_BYTES, main0>>>(px, w_qkv, pp_qkv,
                                                         NQKV, NHID, 640);
        reduce_kernel<0><<<(32 * NQKV + 255) / 256, 256, 0, main0>>>(
            pp_qkv, b_qkv, pqkv, NQKV, 4, nullptr, nullptr);

        rope_kernel<<<NB, 512, 0, main0>>>(ctx, pqkv);

        dim3 ag(NG, NB, NCHUNK);
        attn_hg_kernel<<<ag, 256, 0, main0>>>(ctx, kc, vc, pqkv,
                                              ppm, ppl, ppo);
        dim3 cg(NHEADS, NB);
        attn_combine_kernel<<<cg, 128, 0, main0>>>(ppm, ppl, ppo, pattn);

        dim3 gr2(NHID / GN, 10);
        gemm_tf32_kernel<<<gr2, 256, SMEM_BYTES, main0>>>(pattn, w_out, pp_out,
                                                          NHID, NHID, 256);
        reduce_kernel<0><<<(32 * NHID + 255) / 256, 256, 0, main0>>>(
            pp_out, b_out, pao, NHID, 10, nullptr, nullptr);
    }

    cudaStreamWaitEvent(main0, ev_join, 0);
    reduce_kernel<2><<<(32 * NHID + 255) / 256, 256, 0, main0>>>(
        pp_fc2, b_fc2, out, NHID, 16, pao, hs);
}

// round 10
// speedup vs baseline: 1.0294x; 1.0294x over previous
#include <cuda_runtime.h>
#include <math.h>
#include <stdint.h>

constexpr int NB    = 32;
constexpr int NKV   = 2048;
constexpr int NHID  = 2560;
constexpr int NHEADS= 32;
constexpr int NHD   = 80;
constexpr int NNI   = 10240;
constexpr int NQKV  = 3 * NHID;
constexpr int ASPLIT= 16;
constexpr int ATOK  = 128;

// GEMM tiling: block = 256 thr (8 warps), tile 32m x 128n x 64k
constexpr int GK  = 64;
constexpr int GN  = 128;
constexpr int XS_STRIDE = 68;
constexpr int WS_STRIDE = 64;
constexpr int XS_FLOATS = 32 * XS_STRIDE;
constexpr int WS_FLOATS = GN * WS_STRIDE;
constexpr int SMEM_FLOATS = 2 * (XS_FLOATS + WS_FLOATS);
constexpr int SMEM_BYTES  = SMEM_FLOATS * 4;       // 82944

// Scratch (allocation-free: device globals); per-GEMM partials (stream-safe).
__device__ __align__(16) float g_x[NB * NHID];
__device__ __align__(16) float g_qkv[NB * NQKV];
__device__ __align__(16) float g_attn[NB * NHID];
__device__ __align__(16) float g_hmlp[NB * NNI];
__device__ __align__(16) float g_part_qkv[4  * 32 * NQKV];
__device__ __align__(16) float g_part_out[10 * 32 * NHID];
__device__ __align__(16) float g_part_fc1[4  * 32 * NNI];
__device__ __align__(16) float g_part_fc2[16 * 32 * NHID];
__device__ __align__(16) float g_pm[NB * NHEADS * ASPLIT];
__device__ __align__(16) float g_pl[NB * NHEADS * ASPLIT];
__device__ __align__(16) float g_po[NB * NHEADS * ASPLIT * NHD];

// ---------------------------------------------------------------------------
__device__ __forceinline__ uint32_t f2tf32(float x) {
    uint32_t r;
    asm("cvt.rna.tf32.f32 %0, %1;" : "=r"(r) : "f"(x));
    return r;
}

__device__ __forceinline__ void mma_tf32(float* d, const uint32_t* a,
                                         uint32_t b0, uint32_t b1) {
    asm volatile(
        "mma.sync.aligned.m16n8k8.row.col.f32.tf32.tf32.f32 "
        "{%0,%1,%2,%3}, {%4,%5,%6,%7}, {%8,%9}, {%0,%1,%2,%3};\n"
        : "+f"(d[0]), "+f"(d[1]), "+f"(d[2]), "+f"(d[3])
        : "r"(a[0]), "r"(a[1]), "r"(a[2]), "r"(a[3]), "r"(b0), "r"(b1));
}

__device__ __forceinline__ void cp_async16(void* dst, const void* src) {
    uint32_t s = (uint32_t)__cvta_generic_to_shared(dst);
    asm volatile("cp.async.cg.shared.global [%0], [%1], 16;\n"
                 :: "r"(s), "l"(src));
}

// ---------------------------------------------------------------------------
__global__ __launch_bounds__(256) void ln_kernel(
    const float* __restrict__ hs, const float* __restrict__ gam,
    const float* __restrict__ bet, float* __restrict__ xout)
{
    int b = blockIdx.x;
    const float* row = hs + b * NHID;
    float s = 0.f, s2 = 0.f;
    for (int i = threadIdx.x; i < NHID / 4; i += blockDim.x) {
        float4 v = reinterpret_cast<const float4*>(row)[i];
        s  += v.x + v.y + v.z + v.w;
        s2 += v.x * v.x + v.y * v.y + v.z * v.z + v.w * v.w;
    }
    __shared__ float rs[256], rs2[256];
    rs[threadIdx.x] = s; rs2[threadIdx.x] = s2;
    __syncthreads();
    for (int o = 128; o > 0; o >>= 1) {
        if (threadIdx.x < o) {
            rs[threadIdx.x]  += rs[threadIdx.x + o];
            rs2[threadIdx.x] += rs2[threadIdx.x + o];
        }
        __syncthreads();
    }
    float mu  = rs[0] / NHID;
    float var = rs2[0] / NHID - mu * mu;
    float inv = rsqrtf(var + 1e-5f);
    for (int i = threadIdx.x; i < NHID; i += blockDim.x) {
        xout[b * NHID + i] = (row[i] - mu) * inv * gam[i] + bet[i];
    }
}

// ---------------------------------------------------------------------------
// tf32 split-K GEMM, cp.async double-buffered. 256 thr = 8 warps.
// ---------------------------------------------------------------------------
__global__ __launch_bounds__(256) void gemm_tf32_kernel(
    const float* __restrict__ X, const float* __restrict__ W,
    float* __restrict__ part, int N, int K, int Kper)
{
    extern __shared__ float sm[];
    float* XsBuf[2] = { sm, sm + XS_FLOATS };
    float* WsBuf[2] = { sm + 2 * XS_FLOATS, sm + 2 * XS_FLOATS + WS_FLOATS };

    int tid  = threadIdx.x;
    int w    = tid >> 5;
    int lane = tid & 31;
    int g    = lane >> 2;
    int t    = lane & 3;

    int nbase  = blockIdx.x * GN;
    int ks     = blockIdx.y * Kper;
    int ntiles = Kper / GK;

    float d[2][2][4];
#pragma unroll
    for (int m = 0; m < 2; m++)
#pragma unroll
        for (int s = 0; s < 2; s++)
#pragma unroll
            for (int f = 0; f < 4; f++) d[m][s][f] = 0.f;

    auto stageW = [&](int st, int kt) {
        float* ws = WsBuf[st];
#pragma unroll
        for (int i = 0; i < 8; i++) {
            int c   = tid + i * 256;
            int row = c >> 4;
            int cc  = (c & 15) * 4;
            int pc  = cc ^ ((row & 7) << 2);
            cp_async16(ws + row * WS_STRIDE + pc,
                       W + (size_t)(nbase + row) * K + kt + cc);
        }
        asm volatile("cp.async.commit_group;\n");
    };
    float4 xr[2];
    auto loadX = [&](int kt) {
#pragma unroll
        for (int i = 0; i < 2; i++) {
            int c   = tid + i * 256;
            int row = c >> 4;
            int cc  = (c & 15) * 4;
            xr[i] = *reinterpret_cast<const float4*>(X + (size_t)row * K + kt + cc);
        }
    };
    auto storeX = [&](int st) {
        float* xs = XsBuf[st];
#pragma unroll
        for (int i = 0; i < 2; i++) {
            int c   = tid + i * 256;
            int row = c >> 4;
            int cc  = (c & 15) * 4;
            uint4 u;
            u.x = f2tf32(xr[i].x); u.y = f2tf32(xr[i].y);
            u.z = f2tf32(xr[i].z); u.w = f2tf32(xr[i].w);
            *reinterpret_cast<uint4*>(xs + row * XS_STRIDE + cc) = u;
        }
    };

    stageW(0, ks);
    loadX(ks);
    storeX(0);
    asm volatile("cp.async.wait_group 0;\n");
    __syncthreads();

    for (int it = 0; it < ntiles; it++) {
        int cur = it & 1;
        bool more = (it + 1 < ntiles);
        if (more) {
            stageW(cur ^ 1, ks + (it + 1) * GK);
            loadX(ks + (it + 1) * GK);
        }

        const uint32_t* xs = reinterpret_cast<const uint32_t*>(XsBuf[cur]);
        const float*    ws = WsBuf[cur];
        int sw = (g << 2);
#pragma unroll
        for (int k8 = 0; k8 < GK; k8 += 8) {
            uint32_t a0[4], a1[4];
            a0[0] = xs[(g     ) * XS_STRIDE + k8 + t];
            a0[1] = xs[(g +  8) * XS_STRIDE + k8 + t];
            a0[2] = xs[(g     ) * XS_STRIDE + k8 + t + 4];
            a0[3] = xs[(g +  8) * XS_STRIDE + k8 + t + 4];
            a1[0] = xs[(g + 16) * XS_STRIDE + k8 + t];
            a1[1] = xs[(g + 24) * XS_STRIDE + k8 + t];
            a1[2] = xs[(g + 16) * XS_STRIDE + k8 + t + 4];
            a1[3] = xs[(g + 24) * XS_STRIDE + k8 + t + 4];
#pragma unroll
            for (int s = 0; s < 2; s++) {
                int row = w * 16 + s * 8 + g;
                uint32_t b0 = f2tf32(ws[row * WS_STRIDE + ((k8 + t    ) ^ sw)]);
                uint32_t b1 = f2tf32(ws[row * WS_STRIDE + ((k8 + t + 4) ^ sw)]);
                mma_tf32(d[0][s], a0, b0, b1);
                mma_tf32(d[1][s], a1, b0, b1);
            }
        }

        if (more) {
            storeX(cur ^ 1);
            asm volatile("cp.async.wait_group 0;\n");
        }
        __syncthreads();
    }

    float* pbase = part + (size_t)blockIdx.y * 32 * N;
#pragma unroll
    for (int m = 0; m < 2; m++) {
#pragma unroll
        for (int s = 0; s < 2; s++) {
            int col = nbase + w * 16 + s * 8 + 2 * t;
            int r0  = g + m * 16;
            float2 lo = make_float2(d[m][s][0], d[m][s][1]);
            float2 hi = make_float2(d[m][s][2], d[m][s][3]);
            *reinterpret_cast<float2*>(pbase + (size_t)r0 * N + col)       = lo;
            *reinterpret_cast<float2*>(pbase + (size_t)(r0 + 8) * N + col) = hi;
        }
    }
}

// ---------------------------------------------------------------------------
// split-K reduce + bias + epilogue. EPI: 0 = bias only, 1 = gelu(tanh)
// ---------------------------------------------------------------------------
template <int EPI>
__global__ __launch_bounds__(256) void reduce_kernel(
    const float* __restrict__ part, const float* __restrict__ bias,
    float* __restrict__ C, int N, int KS)
{
    int id = blockIdx.x * 256 + threadIdx.x;
    if (id >= 32 * N) return;
    int j = id % N;
    float s = 0.f;
    for (int z = 0; z < KS; z++) s += part[(size_t)z * 32 * N + id];
    float val = s + bias[j];
    if (EPI == 1) {
        float u = val;
        float th = tanhf(0.7978845608028654f * (u + 0.044715f * u * u * u));
        val = 0.5f * u * (1.f + th);
    }
    C[id] = val;
}

// Final fused reduce: out = Σpa + ba + Σpb + bb + residual
__global__ __launch_bounds__(256) void reduce_final_kernel(
    const float* __restrict__ pa, int ksa, const float* __restrict__ ba,
    const float* __restrict__ pb, int ksb, const float* __restrict__ bb,
    const float* __restrict__ resid, float* __restrict__ C, int N)
{
    int id = blockIdx.x * 256 + threadIdx.x;
    if (id >= 32 * N) return;
    int j = id % N;
    float s = 0.f;
    for (int z = 0; z < ksa; z++) s += pa[(size_t)z * 32 * N + id];
    for (int z = 0; z < ksb; z++) s += pb[(size_t)z * 32 * N + id];
    C[id] = s + ba[j] + bb[j] + resid[id];
}

// ---------------------------------------------------------------------------
__global__ __launch_bounds__(512) void rope_kernel(
    const int* __restrict__ ctxl, float* __restrict__ qkv)
{
    int b = blockIdx.x;
    int t = threadIdx.x;
    int h = t >> 4;
    int i = t & 15;
    float pos = (float)ctxl[b];
    float inv_freq = expf(-(float)(2 * i) / 32.0f * 9.210340371976184f);
    float ang = pos * inv_freq;
    float sn, cs;
    sincosf(ang, &sn, &cs);

    float* q = qkv + (size_t)b * NQKV + h * NHD;
    float x1 = q[i], x2 = q[i + 16];
    q[i]      = x1 * cs - x2 * sn;
    q[i + 16] = x2 * cs + x1 * sn;

    float* k = qkv + (size_t)b * NQKV + NHID + h * NHD;
    x1 = k[i]; x2 = k[i + 16];
    k[i]      = x1 * cs - x2 * sn;
    k[i + 16] = x2 * cs + x1 * sn;
}

// ---------------------------------------------------------------------------
// Flash-decode attention, split-KV (R8 design, ATOK=128/ASPLIT=16).
// Pass 1 streams loads; per-lane partials to smem (stride 21, conflict-free).
// ---------------------------------------------------------------------------
__global__ __launch_bounds__(256) void attn_split_kernel(
    const int* __restrict__ ctxl,
    const float* __restrict__ kc, const float* __restrict__ vc,
    const float* __restrict__ qkv,
    float* __restrict__ pm, float* __restrict__ pl, float* __restrict__ po)
{
    __shared__ float  sPart[ATOK * 21];
    __shared__ float  sP[ATOK];
    __shared__ float4 sQ[20];
    __shared__ float  sRed[256];
    __shared__ float  sAcc[8][80];

    int h = blockIdx.x, b = blockIdx.y, z = blockIdx.z;
    int tid = threadIdx.x;
    int w = tid >> 5, lane = tid & 31;
    int ctx = ctxl[b];
    int L = ctx + 1;
    int s0 = z * ATOK;
    int s1 = min(L, s0 + ATOK);
    int cnt = s1 - s0;
    int pidx = ((b * NHEADS + h) * ASPLIT + z);

    if (s0 >= L) {
        if (tid == 0) { pm[pidx] = -1e30f; pl[pidx] = 0.f; }
        if (tid < NHD) po[(size_t)pidx * NHD + tid] = 0.f;
        return;
    }

    const float* qp = qkv + (size_t)b * NQKV + h * NHD;
    if (tid < 20) sQ[tid] = reinterpret_cast<const float4*>(qp)[tid];
    __syncthreads();

    const float scale = 0.11180339887498948f; // 80^-0.5
    const float* knew = qkv + (size_t)b * NQKV + NHID + h * NHD;
    const float* vnew = qkv + (size_t)b * NQKV + 2 * NHID + h * NHD;

    // Pass 1: pure load+FMA+STS stream, 4 rows per warp iteration.
    float4 q4 = (lane < 20) ? sQ[lane] : make_float4(0.f, 0.f, 0.f, 0.f);
    for (int sb = s0 + w * 4; sb < s1; sb += 32) {
        float4 k0, k1, k2, k3;
        k0 = k1 = k2 = k3 = make_float4(0.f, 0.f, 0.f, 0.f);
        if (lane < 20) {
            const float* r0 = (sb     == ctx) ? knew : kc + (((size_t)b * NKV + sb    ) * NHEADS + h) * NHD;
            k0 = reinterpret_cast<const float4*>(r0)[lane];
            if (sb + 1 < s1) {
                const float* r1 = (sb + 1 == ctx) ? knew : kc + (((size_t)b * NKV + sb + 1) * NHEADS + h) * NHD;
                k1 = reinterpret_cast<const float4*>(r1)[lane];
            }
            if (sb + 2 < s1) {
                const float* r2 = (sb + 2 == ctx) ? knew : kc + (((size_t)b * NKV + sb + 2) * NHEADS + h) * NHD;
                k2 = reinterpret_cast<const float4*>(r2)[lane];
            }
            if (sb + 3 < s1) {
                const float* r3 = (sb + 3 == ctx) ? knew : kc + (((size_t)b * NKV + sb + 3) * NHEADS + h) * NHD;
                k3 = reinterpret_cast<const float4*>(r3)[lane];
            }
            float p0 = k0.x * q4.x + k0.y * q4.y + k0.z * q4.z + k0.w * q4.w;
            float p1 = k1.x * q4.x + k1.y * q4.y + k1.z * q4.z + k1.w * q4.w;
            float p2 = k2.x * q4.x + k2.y * q4.y + k2.z * q4.z + k2.w * q4.w;
            float p3 = k3.x * q4.x + k3.y * q4.y + k3.z * q4.z + k3.w * q4.w;
            sPart[(sb - s0) * 21 + lane] = p0;
            if (sb + 1 < s1) sPart[(sb + 1 - s0) * 21 + lane] = p1;
            if (sb + 2 < s1) sPart[(sb + 2 - s0) * 21 + lane] = p2;
            if (sb + 3 < s1) sPart[(sb + 3 - s0) * 21 + lane] = p3;
        }
    }
    __syncthreads();

    // Softmax phase: thread tid owns token tid; sum its 20 partials.
    float myv = -1e30f;
    if (tid < cnt) {
        float s = 0.f;
#pragma unroll
        for (int j = 0; j < 20; j++) s += sPart[tid * 21 + j];
        myv = s * scale;
    }
    sRed[tid] = myv;
    __syncthreads();
    for (int o = 128; o > 0; o >>= 1) {
        if (tid < o) sRed[tid] = fmaxf(sRed[tid], sRed[tid + o]);
        __syncthreads();
    }
    float m = sRed[0];
    __syncthreads();

    float e = (tid < cnt) ? __expf(myv - m) : 0.f;
    if (tid < cnt) sP[tid] = e;
    sRed[tid] = e;
    __syncthreads();
    for (int o = 128; o > 0; o >>= 1) {
        if (tid < o) sRed[tid] += sRed[tid + o];
        __syncthreads();
    }
    float l = sRed[0];
    __syncthreads();

    // Pass 2: weighted V via float4 loads, 4 rows per iteration.
    float4 acc = make_float4(0.f, 0.f, 0.f, 0.f);
    for (int sb = s0 + w * 4; sb < s1; sb += 32) {
        float4 v0, v1, v2, v3;
        v0 = v1 = v2 = v3 = make_float4(0.f, 0.f, 0.f, 0.f);
        if (lane < 20) {
            const float* r0 = (sb     == ctx) ? vnew : vc + (((size_t)b * NKV + sb    ) * NHEADS + h) * NHD;
            v0 = reinterpret_cast<const float4*>(r0)[lane];
            if (sb + 1 < s1) {
                const float* r1 = (sb + 1 == ctx) ? vnew : vc + (((size_t)b * NKV + sb + 1) * NHEADS + h) * NHD;
                v1 = reinterpret_cast<const float4*>(r1)[lane];
            }
            if (sb + 2 < s1) {
                const float* r2 = (sb + 2 == ctx) ? vnew : vc + (((size_t)b * NKV + sb + 2) * NHEADS + h) * NHD;
                v2 = reinterpret_cast<const float4*>(r2)[lane];
            }
            if (sb + 3 < s1) {
                const float* r3 = (sb + 3 == ctx) ? vnew : vc + (((size_t)b * NKV + sb + 3) * NHEADS + h) * NHD;
                v3 = reinterpret_cast<const float4*>(r3)[lane];
            }
        }
        float p0 = sP[sb - s0];
        float p1 = (sb + 1 < s1) ? sP[sb + 1 - s0] : 0.f;
        float p2 = (sb + 2 < s1) ? sP[sb + 2 - s0] : 0.f;
        float p3 = (sb + 3 < s1) ? sP[sb + 3 - s0] : 0.f;
        acc.x += p0 * v0.x + p1 * v1.x + p2 * v2.x + p3 * v3.x;
        acc.y += p0 * v0.y + p1 * v1.y + p2 * v2.y + p3 * v3.y;
        acc.z += p0 * v0.z + p1 * v1.z + p2 * v2.z + p3 * v3.z;
        acc.w += p0 * v0.w + p1 * v1.w + p2 * v2.w + p3 * v3.w;
    }
    if (lane < 20) {
        sAcc[w][lane * 4 + 0] = acc.x;
        sAcc[w][lane * 4 + 1] = acc.y;
        sAcc[w][lane * 4 + 2] = acc.z;
        sAcc[w][lane * 4 + 3] = acc.w;
    }
    __syncthreads();

    if (tid < NHD) {
        float s = 0.f;
#pragma unroll
        for (int ww = 0; ww < 8; ww++) s += sAcc[ww][tid];
        po[(size_t)pidx * NHD + tid] = s;
    }
    if (tid == 0) { pm[pidx] = m; pl[pidx] = l; }
}

// ---------------------------------------------------------------------------
__global__ __launch_bounds__(128) void attn_combine_kernel(
    const float* __restrict__ pm, const float* __restrict__ pl,
    const float* __restrict__ po, float* __restrict__ attn)
{
    int h = blockIdx.x, b = blockIdx.y;
    int tid = threadIdx.x;
    if (tid >= NHD) return;
    int base = (b * NHEADS + h) * ASPLIT;

    float M = -1e30f;
#pragma unroll
    for (int z = 0; z < ASPLIT; z++) M = fmaxf(M, pm[base + z]);
    float den = 0.f, num = 0.f;
#pragma unroll
    for (int z = 0; z < ASPLIT; z++) {
        float wz = __expf(pm[base + z] - M);
        den += wz * pl[base + z];
        num += wz * po[(size_t)(base + z) * NHD + tid];
    }
    attn[(size_t)b * NHID + h * NHD + tid] = num / den;
}

// ---------------------------------------------------------------------------
extern "C" void kernel_launch(void* const* d_in, const int* in_sizes, int n_in,
                              void* d_out, int out_size)
{
    const float* hs    = (const float*)d_in[0];
    const int*   ctx   = (const int*)  d_in[1];
    const float* kc    = (const float*)d_in[2];
    const float* vc    = (const float*)d_in[3];
    const float* ln_g  = (const float*)d_in[4];
    const float* ln_b  = (const float*)d_in[5];
    const float* w_qkv = (const float*)d_in[6];
    const float* b_qkv = (const float*)d_in[7];
    const float* w_out = (const float*)d_in[8];
    const float* b_out = (const float*)d_in[9];
    const float* w_fc1 = (const float*)d_in[10];
    const float* b_fc1 = (const float*)d_in[11];
    const float* w_fc2 = (const float*)d_in[12];
    const float* b_fc2 = (const float*)d_in[13];
    float* out = (float*)d_out;

    float *px, *pqkv, *pattn, *ph;
    float *pp_qkv, *pp_out, *pp_fc1, *pp_fc2, *ppm, *ppl, *ppo;
    cudaGetSymbolAddress((void**)&px,     g_x);
    cudaGetSymbolAddress((void**)&pqkv,   g_qkv);
    cudaGetSymbolAddress((void**)&pattn,  g_attn);
    cudaGetSymbolAddress((void**)&ph,     g_hmlp);
    cudaGetSymbolAddress((void**)&pp_qkv, g_part_qkv);
    cudaGetSymbolAddress((void**)&pp_out, g_part_out);
    cudaGetSymbolAddress((void**)&pp_fc1, g_part_fc1);
    cudaGetSymbolAddress((void**)&pp_fc2, g_part_fc2);
    cudaGetSymbolAddress((void**)&ppm,    g_pm);
    cudaGetSymbolAddress((void**)&ppl,    g_pl);
    cudaGetSymbolAddress((void**)&ppo,    g_po);

    cudaFuncSetAttribute(gemm_tf32_kernel,
                         cudaFuncAttributeMaxDynamicSharedMemorySize, SMEM_BYTES);

    static cudaStream_t side = nullptr;
    static cudaEvent_t  ev_fork = nullptr, ev_join = nullptr;
    if (side == nullptr) {
        cudaStreamCreateWithFlags(&side, cudaStreamNonBlocking);
        cudaEventCreateWithFlags(&ev_fork, cudaEventDisableTiming);
        cudaEventCreateWithFlags(&ev_join, cudaEventDisableTiming);
    }
    cudaStream_t main0 = (cudaStream_t)0;

    // 1. LayerNorm
    ln_kernel<<<NB, 256, 0, main0>>>(hs, ln_g, ln_b, px);

    cudaEventRecord(ev_fork, main0);
    cudaStreamWaitEvent(side, ev_fork, 0);

    // ---- Track B (side): fc1 -> gelu -> fc2 (partials only) ----
    {
        dim3 gr(NNI / GN, 4);
        gemm_tf32_kernel<<<gr, 256, SMEM_BYTES, side>>>(px, w_fc1, pp_fc1,
                                                        NNI, NHID, 640);
        reduce_kernel<1><<<(32 * NNI + 255) / 256, 256, 0, side>>>(
            pp_fc1, b_fc1, ph, NNI, 4);
        dim3 gr2(NHID / GN, 16);
        gemm_tf32_kernel<<<gr2, 256, SMEM_BYTES, side>>>(ph, w_fc2, pp_fc2,
                                                         NHID, NNI, 640);
        cudaEventRecord(ev_join, side);
    }

    // ---- Track A (main): qkv -> rope -> attention -> out-proj (partials) ----
    {
        dim3 gr(NQKV / GN, 4);   // 240 blocks: single wave at 2 blocks/SM
        gemm_tf32_kernel<<<gr, 256, SMEM_BYTES, main0>>>(px, w_qkv, pp_qkv,
                                                         NQKV, NHID, 640);
        reduce_kernel<0><<<(32 * NQKV + 255) / 256, 256, 0, main0>>>(
            pp_qkv, b_qkv, pqkv, NQKV, 4);

        rope_kernel<<<NB, 512, 0, main0>>>(ctx, pqkv);

        dim3 ag(NHEADS, NB, ASPLIT);
        attn_split_kernel<<<ag, 256, 0, main0>>>(ctx, kc, vc, pqkv,
                                                 ppm, ppl, ppo);
        dim3 cg(NHEADS, NB);
        attn_combine_kernel<<<cg, 128, 0, main0>>>(ppm, ppl, ppo, pattn);

        dim3 gr2(NHID / GN, 10);
        gemm_tf32_kernel<<<gr2, 256, SMEM_BYTES, main0>>>(pattn, w_out, pp_out,
                                                          NHID, NHID, 256);
    }

    // Join: single fused reduce consumes out-proj partials + fc2 partials
    // + both biases + residual.
    cudaStreamWaitEvent(main0, ev_join, 0);
    reduce_final_kernel<<<(32 * NHID + 255) / 256, 256, 0, main0>>>(
        pp_out, 10, b_out, pp_fc2, 16, b_fc2, hs, out, NHID);
}

// round 11
// speedup vs baseline: 1.0783x; 1.0475x over previous
#include <cuda_runtime.h>
#include <math.h>
#include <stdint.h>

constexpr int NB    = 32;
constexpr int NKV   = 2048;
constexpr int NHID  = 2560;
constexpr int NHEADS= 32;
constexpr int NHD   = 80;
constexpr int NNI   = 10240;
constexpr int NQKV  = 3 * NHID;
constexpr int ASPLIT= 8;
constexpr int ATOK  = 256;

// GEMM tiling: block = 256 thr (8 warps), tile 32m x 128n x 32k
constexpr int GK  = 32;
constexpr int GN  = 128;
constexpr int XS_STRIDE = 36;   // 32 + pad, 144B rows (16B aligned)
constexpr int WS_STRIDE = 32;
constexpr int XS_FLOATS = 32 * XS_STRIDE;          // 1152
constexpr int WS_FLOATS = GN * WS_STRIDE;          // 4096
constexpr int SMEM_FLOATS = 2 * (XS_FLOATS + WS_FLOATS);
constexpr int SMEM_BYTES  = SMEM_FLOATS * 4;       // 41984

// Scratch (allocation-free: device globals); per-GEMM partials (stream-safe).
__device__ __align__(16) float g_x[NB * NHID];
__device__ __align__(16) float g_qkv[NB * NQKV];
__device__ __align__(16) float g_attn[NB * NHID];
__device__ __align__(16) float g_hmlp[NB * NNI];
__device__ __align__(16) float g_part_qkv[4  * 32 * NQKV];
__device__ __align__(16) float g_part_out[10 * 32 * NHID];
__device__ __align__(16) float g_part_fc1[4  * 32 * NNI];
__device__ __align__(16) float g_part_fc2[16 * 32 * NHID];
__device__ __align__(16) float g_pm[NB * NHEADS * ASPLIT];
__device__ __align__(16) float g_pl[NB * NHEADS * ASPLIT];
__device__ __align__(16) float g_po[NB * NHEADS * ASPLIT * NHD];

// ---------------------------------------------------------------------------
__device__ __forceinline__ uint32_t f2tf32(float x) {
    uint32_t r;
    asm("cvt.rna.tf32.f32 %0, %1;" : "=r"(r) : "f"(x));
    return r;
}

__device__ __forceinline__ void mma_tf32(float* d, const uint32_t* a,
                                         uint32_t b0, uint32_t b1) {
    asm volatile(
        "mma.sync.aligned.m16n8k8.row.col.f32.tf32.tf32.f32 "
        "{%0,%1,%2,%3}, {%4,%5,%6,%7}, {%8,%9}, {%0,%1,%2,%3};\n"
        : "+f"(d[0]), "+f"(d[1]), "+f"(d[2]), "+f"(d[3])
        : "r"(a[0]), "r"(a[1]), "r"(a[2]), "r"(a[3]), "r"(b0), "r"(b1));
}

__device__ __forceinline__ void cp_async16(void* dst, const void* src) {
    uint32_t s = (uint32_t)__cvta_generic_to_shared(dst);
    asm volatile("cp.async.cg.shared.global [%0], [%1], 16;\n"
                 :: "r"(s), "l"(src));
}

// ---------------------------------------------------------------------------
__global__ __launch_bounds__(256) void ln_kernel(
    const float* __restrict__ hs, const float* __restrict__ gam,
    const float* __restrict__ bet, float* __restrict__ xout)
{
    int b = blockIdx.x;
    const float* row = hs + b * NHID;
    float s = 0.f, s2 = 0.f;
    for (int i = threadIdx.x; i < NHID / 4; i += blockDim.x) {
        float4 v = reinterpret_cast<const float4*>(row)[i];
        s  += v.x + v.y + v.z + v.w;
        s2 += v.x * v.x + v.y * v.y + v.z * v.z + v.w * v.w;
    }
    __shared__ float rs[256], rs2[256];
    rs[threadIdx.x] = s; rs2[threadIdx.x] = s2;
    __syncthreads();
    for (int o = 128; o > 0; o >>= 1) {
        if (threadIdx.x < o) {
            rs[threadIdx.x]  += rs[threadIdx.x + o];
            rs2[threadIdx.x] += rs2[threadIdx.x + o];
        }
        __syncthreads();
    }
    float mu  = rs[0] / NHID;
    float var = rs2[0] / NHID - mu * mu;
    float inv = rsqrtf(var + 1e-5f);
    for (int i = threadIdx.x; i < NHID; i += blockDim.x) {
        xout[b * NHID + i] = (row[i] - mu) * inv * gam[i] + bet[i];
    }
}

// ---------------------------------------------------------------------------
// tf32 split-K GEMM, cp.async double-buffered. GK=32 -> 42KB smem,
// 3 blocks/SM (reg-bound), 24 warps for latency hiding.
// ---------------------------------------------------------------------------
__global__ __launch_bounds__(256) void gemm_tf32_kernel(
    const float* __restrict__ X, const float* __restrict__ W,
    float* __restrict__ part, int N, int K, int Kper)
{
    extern __shared__ float sm[];
    float* XsBuf[2] = { sm, sm + XS_FLOATS };
    float* WsBuf[2] = { sm + 2 * XS_FLOATS, sm + 2 * XS_FLOATS + WS_FLOATS };

    int tid  = threadIdx.x;
    int w    = tid >> 5;
    int lane = tid & 31;
    int g    = lane >> 2;
    int t    = lane & 3;

    int nbase  = blockIdx.x * GN;
    int ks     = blockIdx.y * Kper;
    int ntiles = Kper / GK;

    float d[2][2][4];
#pragma unroll
    for (int m = 0; m < 2; m++)
#pragma unroll
        for (int s = 0; s < 2; s++)
#pragma unroll
            for (int f = 0; f < 4; f++) d[m][s][f] = 0.f;

    auto stageW = [&](int st, int kt) {
        float* ws = WsBuf[st];
#pragma unroll
        for (int i = 0; i < 4; i++) {
            int c   = tid + i * 256;      // 0..1023 chunks
            int row = c >> 3;             // 0..127
            int cc  = (c & 7) * 4;        // 0..28
            int pc  = cc ^ ((row & 7) << 2);
            cp_async16(ws + row * WS_STRIDE + pc,
                       W + (size_t)(nbase + row) * K + kt + cc);
        }
        asm volatile("cp.async.commit_group;\n");
    };
    float4 xr;
    auto loadX = [&](int kt) {
        int row = tid >> 3;               // 0..31
        int cc  = (tid & 7) * 4;
        xr = *reinterpret_cast<const float4*>(X + (size_t)row * K + kt + cc);
    };
    auto storeX = [&](int st) {
        float* xs = XsBuf[st];
        int row = tid >> 3;
        int cc  = (tid & 7) * 4;
        uint4 u;
        u.x = f2tf32(xr.x); u.y = f2tf32(xr.y);
        u.z = f2tf32(xr.z); u.w = f2tf32(xr.w);
        *reinterpret_cast<uint4*>(xs + row * XS_STRIDE + cc) = u;
    };

    stageW(0, ks);
    loadX(ks);
    storeX(0);
    asm volatile("cp.async.wait_group 0;\n");
    __syncthreads();

    for (int it = 0; it < ntiles; it++) {
        int cur = it & 1;
        bool more = (it + 1 < ntiles);
        if (more) {
            stageW(cur ^ 1, ks + (it + 1) * GK);
            loadX(ks + (it + 1) * GK);
        }

        const uint32_t* xs = reinterpret_cast<const uint32_t*>(XsBuf[cur]);
        const float*    ws = WsBuf[cur];
        int sw = (g << 2);
#pragma unroll
        for (int k8 = 0; k8 < GK; k8 += 8) {
            uint32_t a0[4], a1[4];
            a0[0] = xs[(g     ) * XS_STRIDE + k8 + t];
            a0[1] = xs[(g +  8) * XS_STRIDE + k8 + t];
            a0[2] = xs[(g     ) * XS_STRIDE + k8 + t + 4];
            a0[3] = xs[(g +  8) * XS_STRIDE + k8 + t + 4];
            a1[0] = xs[(g + 16) * XS_STRIDE + k8 + t];
            a1[1] = xs[(g + 24) * XS_STRIDE + k8 + t];
            a1[2] = xs[(g + 16) * XS_STRIDE + k8 + t + 4];
            a1[3] = xs[(g + 24) * XS_STRIDE + k8 + t + 4];
#pragma unroll
            for (int s = 0; s < 2; s++) {
                int row = w * 16 + s * 8 + g;
                uint32_t b0 = f2tf32(ws[row * WS_STRIDE + ((k8 + t    ) ^ sw)]);
                uint32_t b1 = f2tf32(ws[row * WS_STRIDE + ((k8 + t + 4) ^ sw)]);
                mma_tf32(d[0][s], a0, b0, b1);
                mma_tf32(d[1][s], a1, b0, b1);
            }
        }

        if (more) {
            storeX(cur ^ 1);
            asm volatile("cp.async.wait_group 0;\n");
        }
        __syncthreads();
    }

    float* pbase = part + (size_t)blockIdx.y * 32 * N;
#pragma unroll
    for (int m = 0; m < 2; m++) {
#pragma unroll
        for (int s = 0; s < 2; s++) {
            int col = nbase + w * 16 + s * 8 + 2 * t;
            int r0  = g + m * 16;
            float2 lo = make_float2(d[m][s][0], d[m][s][1]);
            float2 hi = make_float2(d[m][s][2], d[m][s][3]);
            *reinterpret_cast<float2*>(pbase + (size_t)r0 * N + col)       = lo;
            *reinterpret_cast<float2*>(pbase + (size_t)(r0 + 8) * N + col) = hi;
        }
    }
}

// ---------------------------------------------------------------------------
// split-K reduce + bias + epilogue. EPI: 0 = bias only, 1 = gelu(tanh)
// ---------------------------------------------------------------------------
template <int EPI>
__global__ __launch_bounds__(256) void reduce_kernel(
    const float* __restrict__ part, const float* __restrict__ bias,
    float* __restrict__ C, int N, int KS)
{
    int id = blockIdx.x * 256 + threadIdx.x;
    if (id >= 32 * N) return;
    int j = id % N;
    float s = 0.f;
    for (int z = 0; z < KS; z++) s += part[(size_t)z * 32 * N + id];
    float val = s + bias[j];
    if (EPI == 1) {
        float u = val;
        float th = tanhf(0.7978845608028654f * (u + 0.044715f * u * u * u));
        val = 0.5f * u * (1.f + th);
    }
    C[id] = val;
}

// qkv reduce with RoPE fused. Threads owning rotary dim hd<16 also compute
// the partner element (hd+16) and write both rotated values; threads owning
// hd in [16,32) of q/k regions skip their write.
__global__ __launch_bounds__(256) void reduce_qkv_rope_kernel(
    const float* __restrict__ part, const float* __restrict__ bias,
    const int* __restrict__ ctxl, float* __restrict__ C, int KS)
{
    int id = blockIdx.x * 256 + threadIdx.x;
    if (id >= 32 * NQKV) return;
    int b   = id / NQKV;
    int pos = id % NQKV;
    int region = pos / NHID;      // 0=q, 1=k, 2=v
    int hd  = (pos % NHID) % NHD;

    float s = 0.f;
    for (int z = 0; z < KS; z++) s += part[(size_t)z * 32 * NQKV + id];
    float val = s + bias[pos];

    if (region == 2 || hd >= 32) {           // no rope
        C[id] = val;
        return;
    }
    if (hd >= 16) return;                    // written by partner thread

    // compute partner (hd+16)
    float s2 = 0.f;
    for (int z = 0; z < KS; z++) s2 += part[(size_t)z * 32 * NQKV + id + 16];
    float val2 = s2 + bias[pos + 16];

    float posf = (float)ctxl[b];
    float inv_freq = expf(-(float)(2 * hd) / 32.0f * 9.210340371976184f);
    float sn, cs;
    sincosf(posf * inv_freq, &sn, &cs);
    C[id]      = val * cs - val2 * sn;
    C[id + 16] = val2 * cs + val * sn;
}

// Final fused reduce: out = Σpa + ba + Σpb + bb + residual
__global__ __launch_bounds__(256) void reduce_final_kernel(
    const float* __restrict__ pa, int ksa, const float* __restrict__ ba,
    const float* __restrict__ pb, int ksb, const float* __restrict__ bb,
    const float* __restrict__ resid, float* __restrict__ C, int N)
{
    int id = blockIdx.x * 256 + threadIdx.x;
    if (id >= 32 * N) return;
    int j = id % N;
    float s = 0.f;
    for (int z = 0; z < ksa; z++) s += pa[(size_t)z * 32 * N + id];
    for (int z = 0; z < ksb; z++) s += pb[(size_t)z * 32 * N + id];
    C[id] = s + ba[j] + bb[j] + resid[id];
}

// ---------------------------------------------------------------------------
// Flash-decode attention, split-KV (R8 design: ATOK=256/ASPLIT=8).
// ---------------------------------------------------------------------------
__global__ __launch_bounds__(256) void attn_split_kernel(
    const int* __restrict__ ctxl,
    const float* __restrict__ kc, const float* __restrict__ vc,
    const float* __restrict__ qkv,
    float* __restrict__ pm, float* __restrict__ pl, float* __restrict__ po)
{
    __shared__ float  sPart[ATOK * 21];
    __shared__ float  sP[ATOK];
    __shared__ float4 sQ[20];
    __shared__ float  sRed[256];
    __shared__ float  sAcc[8][80];

    int h = blockIdx.x, b = blockIdx.y, z = blockIdx.z;
    int tid = threadIdx.x;
    int w = tid >> 5, lane = tid & 31;
    int ctx = ctxl[b];
    int L = ctx + 1;
    int s0 = z * ATOK;
    int s1 = min(L, s0 + ATOK);
    int cnt = s1 - s0;
    int pidx = ((b * NHEADS + h) * ASPLIT + z);

    if (s0 >= L) {
        if (tid == 0) { pm[pidx] = -1e30f; pl[pidx] = 0.f; }
        if (tid < NHD) po[(size_t)pidx * NHD + tid] = 0.f;
        return;
    }

    const float* qp = qkv + (size_t)b * NQKV + h * NHD;
    if (tid < 20) sQ[tid] = reinterpret_cast<const float4*>(qp)[tid];
    __syncthreads();

    const float scale = 0.11180339887498948f; // 80^-0.5
    const float* knew = qkv + (size_t)b * NQKV + NHID + h * NHD;
    const float* vnew = qkv + (size_t)b * NQKV + 2 * NHID + h * NHD;

    // Pass 1: pure load+FMA+STS stream, 4 rows per warp iteration.
    float4 q4 = (lane < 20) ? sQ[lane] : make_float4(0.f, 0.f, 0.f, 0.f);
    for (int sb = s0 + w * 4; sb < s1; sb += 32) {
        float4 k0, k1, k2, k3;
        k0 = k1 = k2 = k3 = make_float4(0.f, 0.f, 0.f, 0.f);
        if (lane < 20) {
            const float* r0 = (sb     == ctx) ? knew : kc + (((size_t)b * NKV + sb    ) * NHEADS + h) * NHD;
            k0 = reinterpret_cast<const float4*>(r0)[lane];
            if (sb + 1 < s1) {
                const float* r1 = (sb + 1 == ctx) ? knew : kc + (((size_t)b * NKV + sb + 1) * NHEADS + h) * NHD;
                k1 = reinterpret_cast<const float4*>(r1)[lane];
            }
            if (sb + 2 < s1) {
                const float* r2 = (sb + 2 == ctx) ? knew : kc + (((size_t)b * NKV + sb + 2) * NHEADS + h) * NHD;
                k2 = reinterpret_cast<const float4*>(r2)[lane];
            }
            if (sb + 3 < s1) {
                const float* r3 = (sb + 3 == ctx) ? knew : kc + (((size_t)b * NKV + sb + 3) * NHEADS + h) * NHD;
                k3 = reinterpret_cast<const float4*>(r3)[lane];
            }
            float p0 = k0.x * q4.x + k0.y * q4.y + k0.z * q4.z + k0.w * q4.w;
            float p1 = k1.x * q4.x + k1.y * q4.y + k1.z * q4.z + k1.w * q4.w;
            float p2 = k2.x * q4.x + k2.y * q4.y + k2.z * q4.z + k2.w * q4.w;
            float p3 = k3.x * q4.x + k3.y * q4.y + k3.z * q4.z + k3.w * q4.w;
            sPart[(sb - s0) * 21 + lane] = p0;
            if (sb + 1 < s1) sPart[(sb + 1 - s0) * 21 + lane] = p1;
            if (sb + 2 < s1) sPart[(sb + 2 - s0) * 21 + lane] = p2;
            if (sb + 3 < s1) sPart[(sb + 3 - s0) * 21 + lane] = p3;
        }
    }
    __syncthreads();

    // Softmax phase: thread tid owns token tid; sum its 20 partials.
    float myv = -1e30f;
    if (tid < cnt) {
        float s = 0.f;
#pragma unroll
        for (int j = 0; j < 20; j++) s += sPart[tid * 21 + j];
        myv = s * scale;
    }
    sRed[tid] = myv;
    __syncthreads();
    for (int o = 128; o > 0; o >>= 1) {
        if (tid < o) sRed[tid] = fmaxf(sRed[tid], sRed[tid + o]);
        __syncthreads();
    }
    float m = sRed[0];
    __syncthreads();

    float e = (tid < cnt) ? __expf(myv - m) : 0.f;
    if (tid < cnt) sP[tid] = e;
    sRed[tid] = e;
    __syncthreads();
    for (int o = 128; o > 0; o >>= 1) {
        if (tid < o) sRed[tid] += sRed[tid + o];
        __syncthreads();
    }
    float l = sRed[0];
    __syncthreads();

    // Pass 2: weighted V via float4 loads, 4 rows per iteration.
    float4 acc = make_float4(0.f, 0.f, 0.f, 0.f);
    for (int sb = s0 + w * 4; sb < s1; sb += 32) {
        float4 v0, v1, v2, v3;
        v0 = v1 = v2 = v3 = make_float4(0.f, 0.f, 0.f, 0.f);
        if (lane < 20) {
            const float* r0 = (sb     == ctx) ? vnew : vc + (((size_t)b * NKV + sb    ) * NHEADS + h) * NHD;
            v0 = reinterpret_cast<const float4*>(r0)[lane];
            if (sb + 1 < s1) {
                const float* r1 = (sb + 1 == ctx) ? vnew : vc + (((size_t)b * NKV + sb + 1) * NHEADS + h) * NHD;
                v1 = reinterpret_cast<const float4*>(r1)[lane];
            }
            if (sb + 2 < s1) {
                const float* r2 = (sb + 2 == ctx) ? vnew : vc + (((size_t)b * NKV + sb + 2) * NHEADS + h) * NHD;
                v2 = reinterpret_cast<const float4*>(r2)[lane];
            }
            if (sb + 3 < s1) {
                const float* r3 = (sb + 3 == ctx) ? vnew : vc + (((size_t)b * NKV + sb + 3) * NHEADS + h) * NHD;
                v3 = reinterpret_cast<const float4*>(r3)[lane];
            }
        }
        float p0 = sP[sb - s0];
        float p1 = (sb + 1 < s1) ? sP[sb + 1 - s0] : 0.f;
        float p2 = (sb + 2 < s1) ? sP[sb + 2 - s0] : 0.f;
        float p3 = (sb + 3 < s1) ? sP[sb + 3 - s0] : 0.f;
        acc.x += p0 * v0.x + p1 * v1.x + p2 * v2.x + p3 * v3.x;
        acc.y += p0 * v0.y + p1 * v1.y + p2 * v2.y + p3 * v3.y;
        acc.z += p0 * v0.z + p1 * v1.z + p2 * v2.z + p3 * v3.z;
        acc.w += p0 * v0.w + p1 * v1.w + p2 * v2.w + p3 * v3.w;
    }
    if (lane < 20) {
        sAcc[w][lane * 4 + 0] = acc.x;
        sAcc[w][lane * 4 + 1] = acc.y;
        sAcc[w][lane * 4 + 2] = acc.z;
        sAcc[w][lane * 4 + 3] = acc.w;
    }
    __syncthreads();

    if (tid < NHD) {
        float s = 0.f;
#pragma unroll
        for (int ww = 0; ww < 8; ww++) s += sAcc[ww][tid];
        po[(size_t)pidx * NHD + tid] = s;
    }
    if (tid == 0) { pm[pidx] = m; pl[pidx] = l; }
}

// ---------------------------------------------------------------------------
__global__ __launch_bounds__(128) void attn_combine_kernel(
    const float* __restrict__ pm, const float* __restrict__ pl,
    const float* __restrict__ po, float* __restrict__ attn)
{
    int h = blockIdx.x, b = blockIdx.y;
    int tid = threadIdx.x;
    if (tid >= NHD) return;
    int base = (b * NHEADS + h) * ASPLIT;

    float M = -1e30f;
#pragma unroll
    for (int z = 0; z < ASPLIT; z++) M = fmaxf(M, pm[base + z]);
    float den = 0.f, num = 0.f;
#pragma unroll
    for (int z = 0; z < ASPLIT; z++) {
        float wz = __expf(pm[base + z] - M);
        den += wz * pl[base + z];
        num += wz * po[(size_t)(base + z) * NHD + tid];
    }
    attn[(size_t)b * NHID + h * NHD + tid] = num / den;
}

// ---------------------------------------------------------------------------
extern "C" void kernel_launch(void* const* d_in, const int* in_sizes, int n_in,
                              void* d_out, int out_size)
{
    const float* hs    = (const float*)d_in[0];
    const int*   ctx   = (const int*)  d_in[1];
    const float* kc    = (const float*)d_in[2];
    const float* vc    = (const float*)d_in[3];
    const float* ln_g  = (const float*)d_in[4];
    const float* ln_b  = (const float*)d_in[5];
    const float* w_qkv = (const float*)d_in[6];
    const float* b_qkv = (const float*)d_in[7];
    const float* w_out = (const float*)d_in[8];
    const float* b_out = (const float*)d_in[9];
    const float* w_fc1 = (const float*)d_in[10];
    const float* b_fc1 = (const float*)d_in[11];
    const float* w_fc2 = (const float*)d_in[12];
    const float* b_fc2 = (const float*)d_in[13];
    float* out = (float*)d_out;

    float *px, *pqkv, *pattn, *ph;
    float *pp_qkv, *pp_out, *pp_fc1, *pp_fc2, *ppm, *ppl, *ppo;
    cudaGetSymbolAddress((void**)&px,     g_x);
    cudaGetSymbolAddress((void**)&pqkv,   g_qkv);
    cudaGetSymbolAddress((void**)&pattn,  g_attn);
    cudaGetSymbolAddress((void**)&ph,     g_hmlp);
    cudaGetSymbolAddress((void**)&pp_qkv, g_part_qkv);
    cudaGetSymbolAddress((void**)&pp_out, g_part_out);
    cudaGetSymbolAddress((void**)&pp_fc1, g_part_fc1);
    cudaGetSymbolAddress((void**)&pp_fc2, g_part_fc2);
    cudaGetSymbolAddress((void**)&ppm,    g_pm);
    cudaGetSymbolAddress((void**)&ppl,    g_pl);
    cudaGetSymbolAddress((void**)&ppo,    g_po);

    cudaFuncSetAttribute(gemm_tf32_kernel,
                         cudaFuncAttributeMaxDynamicSharedMemorySize, SMEM_BYTES);

    static cudaStream_t side = nullptr;
    static cudaEvent_t  ev_fork = nullptr, ev_join = nullptr;
    if (side == nullptr) {
        cudaStreamCreateWithFlags(&side, cudaStreamNonBlocking);
        cudaEventCreateWithFlags(&ev_fork, cudaEventDisableTiming);
        cudaEventCreateWithFlags(&ev_join, cudaEventDisableTiming);
    }
    cudaStream_t main0 = (cudaStream_t)0;

    // 1. LayerNorm
    ln_kernel<<<NB, 256, 0, main0>>>(hs, ln_g, ln_b, px);

    cudaEventRecord(ev_fork, main0);
    cudaStreamWaitEvent(side, ev_fork, 0);

    // ---- Track B (side): fc1 -> gelu -> fc2 (partials only) ----
    {
        dim3 gr(NNI / GN, 4);
        gemm_tf32_kernel<<<gr, 256, SMEM_BYTES, side>>>(px, w_fc1, pp_fc1,
                                                        NNI, NHID, 640);
        reduce_kernel<1><<<(32 * NNI + 255) / 256, 256, 0, side>>>(
            pp_fc1, b_fc1, ph, NNI, 4);
        dim3 gr2(NHID / GN, 16);
        gemm_tf32_kernel<<<gr2, 256, SMEM_BYTES, side>>>(ph, w_fc2, pp_fc2,
                                                         NHID, NNI, 640);
        cudaEventRecord(ev_join, side);
    }

    // ---- Track A (main): qkv(+rope fused reduce) -> attention -> out-proj ----
    {
        dim3 gr(NQKV / GN, 4);
        gemm_tf32_kernel<<<gr, 256, SMEM_BYTES, main0>>>(px, w_qkv, pp_qkv,
                                                         NQKV, NHID, 640);
        reduce_qkv_rope_kernel<<<(32 * NQKV + 255) / 256, 256, 0, main0>>>(
            pp_qkv, b_qkv, ctx, pqkv, 4);

        dim3 ag(NHEADS, NB, ASPLIT);
        attn_split_kernel<<<ag, 256, 0, main0>>>(ctx, kc, vc, pqkv,
                                                 ppm, ppl, ppo);
        dim3 cg(NHEADS, NB);
        attn_combine_kernel<<<cg, 128, 0, main0>>>(ppm, ppl, ppo, pattn);

        dim3 gr2(NHID / GN, 10);
        gemm_tf32_kernel<<<gr2, 256, SMEM_BYTES, main0>>>(pattn, w_out, pp_out,
                                                          NHID, NHID, 256);
    }

    // Join: fused final reduce (out-proj partials + fc2 partials + residual)
    cudaStreamWaitEvent(main0, ev_join, 0);
    reduce_final_kernel<<<(32 * NHID + 255) / 256, 256, 0, main0>>>(
        pp_out, 10, b_out, pp_fc2, 16, b_fc2, hs, out, NHID);
}